// round 1
// baseline (speedup 1.0000x reference)
#include <cuda_runtime.h>

// Problem constants (match reference)
#define N1 50000
#define N_LAYERS 3
#define N2 (N1 * N_LAYERS)   // 150000
#define E1 800000
#define E2 2400000
#define D  64
#define LEAKY 0.01f

// Degree array layout inside g_degs
#define OFF_OUT1 0
#define OFF_IN1  (N1)
#define OFF_OUT2 (2 * N1)
#define OFF_IN2  (2 * N1 + N2)
#define DEGS_TOTAL (2 * N1 + 2 * N2)   // 400000

// -------- scratch (device globals; no allocations allowed) --------
__device__ __align__(16) float g_agg1[N1 * D];     // 12.8 MB
__device__ __align__(16) float g_h1[N1 * D];       // 12.8 MB
__device__ __align__(16) float g_agg2[N2 * D];     // 38.4 MB
__device__ __align__(16) float g_degs[DEGS_TOTAL]; // 1.6 MB

// -------- vectorized global reduction (sm_90+) --------
__device__ __forceinline__ void red_add_v4(float* addr, float4 v) {
    asm volatile("red.global.add.v4.f32 [%0], {%1, %2, %3, %4};"
                 :: "l"(addr), "f"(v.x), "f"(v.y), "f"(v.z), "f"(v.w)
                 : "memory");
}

// -------- kernel 1: zero all scratch --------
__global__ void zero_kernel() {
    const int nt  = gridDim.x * blockDim.x;
    const int tid = blockIdx.x * blockDim.x + threadIdx.x;
    const float4 z = make_float4(0.f, 0.f, 0.f, 0.f);
    for (int i = tid; i < N1 * D / 4; i += nt) reinterpret_cast<float4*>(g_agg1)[i] = z;
    for (int i = tid; i < N2 * D / 4; i += nt) reinterpret_cast<float4*>(g_agg2)[i] = z;
    for (int i = tid; i < DEGS_TOTAL / 4; i += nt) reinterpret_cast<float4*>(g_degs)[i] = z;
}

// -------- kernel 2: degree histograms for both graphs --------
__global__ void degrees_kernel(const int* __restrict__ s1, const int* __restrict__ d1,
                               const int* __restrict__ s2, const int* __restrict__ d2) {
    const int t = blockIdx.x * blockDim.x + threadIdx.x;
    if (t < E1) {
        atomicAdd(&g_degs[OFF_OUT1 + s1[t]], 1.f);
        atomicAdd(&g_degs[OFF_IN1  + d1[t]], 1.f);
    }
    if (t < E2) {
        atomicAdd(&g_degs[OFF_OUT2 + s2[t]], 1.f);
        atomicAdd(&g_degs[OFF_IN2  + d2[t]], 1.f);
    }
}

// -------- kernel 3: degrees -> rsqrt(max(deg,1)) in place --------
__global__ void norm_kernel() {
    const int t = blockIdx.x * blockDim.x + threadIdx.x;
    if (t < DEGS_TOTAL) {
        g_degs[t] = rsqrtf(fmaxf(g_degs[t], 1.f));
    }
}

// -------- kernel 4/6: edge scatter-add with fused src norm --------
// GRAPH=1: feat = external x (node_features), agg = g_agg1, norms at OFF_OUT1
// GRAPH=2: feat = g_h1 indexed by (src mod N1), agg = g_agg2, norms at OFF_OUT2
template <int GRAPH>
__global__ void scatter_kernel(const float* __restrict__ feat_ext,
                               const int* __restrict__ src,
                               const int* __restrict__ dst,
                               int nE) {
    const long long t = (long long)blockIdx.x * blockDim.x + threadIdx.x;
    if (t >= (long long)nE * 16) return;
    const int e = (int)(t >> 4);
    const int c = ((int)t & 15) << 2;   // column offset 0..60 step 4

    const int s = src[e];
    const int d = dst[e];

    const float* feat;
    const float* nsrc;
    float* agg;
    int fi = s;
    if (GRAPH == 1) {
        feat = feat_ext;
        nsrc = g_degs + OFF_OUT1;
        agg  = g_agg1;
    } else {
        feat = g_h1;
        nsrc = g_degs + OFF_OUT2;
        agg  = g_agg2;
        if (fi >= 2 * N1)      fi -= 2 * N1;   // tile(h1, (3,1)): row i -> h1[i mod N1]
        else if (fi >= N1)     fi -= N1;
    }

    const float ns = nsrc[s];
    float4 v = *reinterpret_cast<const float4*>(feat + (long long)fi * D + c);
    v.x *= ns; v.y *= ns; v.z *= ns; v.w *= ns;
    red_add_v4(agg + (long long)d * D + c, v);
}

// -------- kernel 5/7: fused (agg * norm_dst) @ W + b, leaky relu --------
// GRAPH=1: in = g_agg1, out = g_h1, N = N1
// GRAPH=2: in = g_agg2, out = d_out, N = N2
template <int GRAPH>
__global__ void gemm_kernel(const float* __restrict__ W,
                            const float* __restrict__ bias,
                            float* __restrict__ out_ext) {
    __shared__ float sW[D * D];     // W[k][j] row-major
    __shared__ float sB[D];
    __shared__ float srow[4][D];

    const float* in  = (GRAPH == 1) ? g_agg1 : g_agg2;
    const float* nd  = (GRAPH == 1) ? (g_degs + OFF_IN1) : (g_degs + OFF_IN2);
    float* out       = (GRAPH == 1) ? g_h1 : out_ext;
    const int N      = (GRAPH == 1) ? N1 : N2;

    const int tx = threadIdx.x;     // 0..63 (output column)
    const int ty = threadIdx.y;     // 0..3  (row within group)
    const int tid = ty * 64 + tx;

    for (int i = tid; i < D * D; i += 256) sW[i] = W[i];
    if (tid < D) sB[tid] = bias[tid];
    __syncthreads();

    const int ROWS_PER_BLOCK = 64;
    const int row0 = blockIdx.x * ROWS_PER_BLOCK;

    for (int rr = 0; rr < ROWS_PER_BLOCK; rr += 4) {
        const int row = row0 + rr + ty;
        __syncthreads();
        if (row < N) {
            srow[ty][tx] = in[(long long)row * D + tx] * nd[row];
        }
        __syncthreads();
        if (row < N) {
            float acc = sB[tx];
#pragma unroll
            for (int k = 0; k < D; k++) {
                acc = fmaf(srow[ty][k], sW[k * D + tx], acc);
            }
            out[(long long)row * D + tx] = (acc > 0.f) ? acc : LEAKY * acc;
        }
    }
}

extern "C" void kernel_launch(void* const* d_in, const int* in_sizes, int n_in,
                              void* d_out, int out_size) {
    const float* x    = (const float*)d_in[0];   // node_features [N1, D]
    const float* WQ   = (const float*)d_in[1];   // [D, D]
    const float* bQ   = (const float*)d_in[2];   // [D]
    const float* WM   = (const float*)d_in[3];   // [D, D]
    const float* bM   = (const float*)d_in[4];   // [D]
    const int*   src1 = (const int*)d_in[5];     // [E1]
    const int*   dst1 = (const int*)d_in[6];     // [E1]
    const int*   src2 = (const int*)d_in[7];     // [E2]
    const int*   dst2 = (const int*)d_in[8];     // [E2]
    float* out = (float*)d_out;                  // [N2, D]

    // 1. zero scratch
    zero_kernel<<<148 * 8, 256>>>();

    // 2. degrees for both graphs
    degrees_kernel<<<(E2 + 255) / 256, 256>>>(src1, dst1, src2, dst2);

    // 3. norms
    norm_kernel<<<(DEGS_TOTAL + 255) / 256, 256>>>();

    // 4. scatter graph 1
    {
        long long total = (long long)E1 * 16;
        scatter_kernel<1><<<(unsigned)((total + 255) / 256), 256>>>(x, src1, dst1, E1);
    }

    // 5. gemm1 + leaky -> g_h1
    {
        dim3 blk(64, 4);
        gemm_kernel<1><<<(N1 + 63) / 64, blk>>>(WQ, bQ, nullptr);
    }

    // 6. scatter graph 2 (reads g_h1 with mod-N1 tiling)
    {
        long long total = (long long)E2 * 16;
        scatter_kernel<2><<<(unsigned)((total + 255) / 256), 256>>>(nullptr, src2, dst2, E2);
    }

    // 7. gemm2 + leaky -> d_out
    {
        dim3 blk(64, 4);
        gemm_kernel<2><<<(N2 + 63) / 64, blk>>>(WM, bM, out);
    }
}

// round 3
// speedup vs baseline: 1.3724x; 1.3724x over previous
#include <cuda_runtime.h>

// Problem constants (match reference)
#define N1 50000
#define N_LAYERS 3
#define N2 (N1 * N_LAYERS)   // 150000
#define E1 800000
#define E2 2400000
#define NE (E1 + E2)         // 3200000
#define D  64
#define LEAKY 0.01f

#define NNODES (N1 + N2)     // 200000 (graph1 nodes, then graph2 nodes)

// scan config
#define SCAN_ITEMS 16
#define SCAN_THREADS 256
#define SCAN_BLOCK (SCAN_ITEMS * SCAN_THREADS)          // 4096
#define SCAN_NBLOCKS ((NNODES + SCAN_BLOCK - 1) / SCAN_BLOCK)  // 49

// -------- scratch (device globals; no allocations allowed) --------
__device__ __align__(16) float g_h1[N1 * D];          // 12.8 MB  (post-conv1 features)
__device__ __align__(16) int   g_outdeg[NNODES];      // out-degree per node (both graphs)
__device__ __align__(16) int   g_indeg[NNODES];       // in-degree per node
__device__ __align__(16) float g_norm_out[NNODES];    // rsqrt(max(outdeg,1))
__device__ __align__(16) float g_norm_in[NNODES];     // rsqrt(max(indeg,1))
__device__ __align__(16) int   g_csr_off[NNODES];     // exclusive scan of in-degrees
__device__ __align__(16) int   g_cursor[NNODES];      // ticket counters (init = csr_off)
__device__ __align__(16) int   g_blocksums[SCAN_NBLOCKS + 1];
__device__ __align__(16) int   g_blockoff[SCAN_NBLOCKS + 1];
__device__ __align__(16) int   g_csr_idx[NE];         // 12.8 MB: feature-row index per edge
__device__ __align__(16) float g_csr_w[NE];           // 12.8 MB: src-side norm per edge

// -------- kernel 1: zero degree counters --------
__global__ void zero_kernel() {
    const int nt  = gridDim.x * blockDim.x;
    const int tid = blockIdx.x * blockDim.x + threadIdx.x;
    for (int i = tid; i < NNODES; i += nt) { g_outdeg[i] = 0; g_indeg[i] = 0; }
}

// -------- kernel 2: degree histograms for both graphs --------
__global__ void degrees_kernel(const int* __restrict__ s1, const int* __restrict__ d1,
                               const int* __restrict__ s2, const int* __restrict__ d2) {
    const int t = blockIdx.x * blockDim.x + threadIdx.x;
    if (t < E1) {
        atomicAdd(&g_outdeg[s1[t]], 1);
        atomicAdd(&g_indeg[d1[t]], 1);
    }
    if (t < E2) {
        atomicAdd(&g_outdeg[N1 + s2[t]], 1);
        atomicAdd(&g_indeg[N1 + d2[t]], 1);
    }
}

// -------- kernel 3: degree -> rsqrt norms --------
__global__ void norm_kernel() {
    const int t = blockIdx.x * blockDim.x + threadIdx.x;
    if (t < NNODES) {
        g_norm_out[t] = rsqrtf(fmaxf((float)g_outdeg[t], 1.f));
        g_norm_in[t]  = rsqrtf(fmaxf((float)g_indeg[t], 1.f));
    }
}

// -------- scan kernel A: per-block exclusive scan of in-degrees --------
__global__ void scan_block_kernel() {
    __shared__ int sdata[SCAN_BLOCK];
    __shared__ int ssum[SCAN_THREADS];
    const int b = blockIdx.x;
    const int t = threadIdx.x;
    const int base_g = b * SCAN_BLOCK;

    // coalesced load
    for (int i = t; i < SCAN_BLOCK; i += SCAN_THREADS) {
        const int gi = base_g + i;
        sdata[i] = (gi < NNODES) ? g_indeg[gi] : 0;
    }
    __syncthreads();

    // each thread grabs its 16 contiguous items into registers
    int v[SCAN_ITEMS];
    int tsum = 0;
    const int lb = t * SCAN_ITEMS;
#pragma unroll
    for (int i = 0; i < SCAN_ITEMS; i++) { v[i] = sdata[lb + i]; tsum += v[i]; }

    // inclusive Hillis-Steele scan of per-thread sums
    ssum[t] = tsum;
    __syncthreads();
    for (int off = 1; off < SCAN_THREADS; off <<= 1) {
        int add = (t >= off) ? ssum[t - off] : 0;
        __syncthreads();
        ssum[t] += add;
        __syncthreads();
    }
    int excl = ssum[t] - tsum;
    if (t == SCAN_THREADS - 1) g_blocksums[b] = ssum[t];

    // write exclusive values back
    int running = excl;
#pragma unroll
    for (int i = 0; i < SCAN_ITEMS; i++) { sdata[lb + i] = running; running += v[i]; }
    __syncthreads();
    for (int i = t; i < SCAN_BLOCK; i += SCAN_THREADS) {
        const int gi = base_g + i;
        if (gi < NNODES) g_csr_off[gi] = sdata[i];
    }
}

// -------- scan kernel B: exclusive scan of block sums (tiny) --------
__global__ void scan_sums_kernel() {
    if (threadIdx.x == 0 && blockIdx.x == 0) {
        int running = 0;
        for (int b = 0; b < SCAN_NBLOCKS; b++) {
            const int s = g_blocksums[b];
            g_blockoff[b] = running;
            running += s;
        }
    }
}

// -------- scan kernel C: add block offsets; init cursors --------
__global__ void scan_add_kernel() {
    const int t = blockIdx.x * blockDim.x + threadIdx.x;
    if (t < NNODES) {
        const int v = g_csr_off[t] + g_blockoff[t / SCAN_BLOCK];
        g_csr_off[t] = v;
        g_cursor[t]  = v;
    }
}

// -------- kernel: CSR fill (counting sort of edges by dst) --------
__global__ void fill_kernel(const int* __restrict__ s1, const int* __restrict__ d1,
                            const int* __restrict__ s2, const int* __restrict__ d2) {
    const int t = blockIdx.x * blockDim.x + threadIdx.x;
    if (t < E1) {
        const int s = s1[t];
        const int pos = atomicAdd(&g_cursor[d1[t]], 1);
        g_csr_idx[pos] = s;
        g_csr_w[pos]   = g_norm_out[s];
    }
    if (t < E2) {
        const int s = s2[t];
        int fi = s;
        if (fi >= 2 * N1)      fi -= 2 * N1;   // tile(h1,(3,1)): row i -> h1[i mod N1]
        else if (fi >= N1)     fi -= N1;
        const int pos = atomicAdd(&g_cursor[N1 + d2[t]], 1);
        g_csr_idx[pos] = fi;
        g_csr_w[pos]   = g_norm_out[N1 + s];
    }
}

// -------- fused gather + norm + GEMM + bias + leaky --------
// 256 threads = 16 groups x 16 lanes; one node per group.
// GRAPH=1: feat=x (ext), out=g_h1, nodes [0,N1)
// GRAPH=2: feat=g_h1, out=d_out, nodes [N1, N1+N2)
template <int GRAPH>
__global__ void gather_gemm_kernel(const float* __restrict__ feat_ext,
                                   const float* __restrict__ W,
                                   const float* __restrict__ bias,
                                   float* __restrict__ out_ext) {
    __shared__ float4 sW4[D * (D / 4)];   // W[k][j] rows as float4: sW4[k*16+c]
    __shared__ float  srow[16][68];       // padded: stride 68 -> conflict-free

    const int tid = threadIdx.x;
    const int grp = tid >> 4;             // 0..15
    const int ln  = tid & 15;             // 0..15

    for (int i = tid; i < D * D / 4; i += 256)
        sW4[i] = reinterpret_cast<const float4*>(W)[i];
    __syncthreads();

    const float* feat = (GRAPH == 1) ? feat_ext : g_h1;
    float* out        = (GRAPH == 1) ? g_h1 : out_ext;
    const int N       = (GRAPH == 1) ? N1 : N2;
    const int base    = (GRAPH == 1) ? 0 : N1;

    const int node = blockIdx.x * 16 + grp;
    if (node >= N) return;
    const int gnode = base + node;

    const int start = g_csr_off[gnode];
    const int cnt   = g_indeg[gnode];
    const float nin = g_norm_in[gnode];

    const float4* f4 = reinterpret_cast<const float4*>(feat);

    // gather: accumulate 4 columns (ln*4 .. ln*4+3) over all in-edges
    float4 acc = make_float4(0.f, 0.f, 0.f, 0.f);
    int j = start;
    const int end = start + cnt;
    for (; j + 1 < end; j += 2) {
        const int   f0 = g_csr_idx[j];
        const int   f1 = g_csr_idx[j + 1];
        const float w0 = g_csr_w[j];
        const float w1 = g_csr_w[j + 1];
        const float4 v0 = f4[f0 * (D / 4) + ln];
        const float4 v1 = f4[f1 * (D / 4) + ln];
        acc.x += w0 * v0.x + w1 * v1.x;
        acc.y += w0 * v0.y + w1 * v1.y;
        acc.z += w0 * v0.z + w1 * v1.z;
        acc.w += w0 * v0.w + w1 * v1.w;
    }
    if (j < end) {
        const int   f0 = g_csr_idx[j];
        const float w0 = g_csr_w[j];
        const float4 v0 = f4[f0 * (D / 4) + ln];
        acc.x += w0 * v0.x; acc.y += w0 * v0.y;
        acc.z += w0 * v0.z; acc.w += w0 * v0.w;
    }
    acc.x *= nin; acc.y *= nin; acc.z *= nin; acc.w *= nin;

    // stage the full 64-wide row in smem for the GEMM
    *reinterpret_cast<float4*>(&srow[grp][ln * 4]) = acc;
    __syncwarp();

    // GEMM: this thread computes output columns ln*4 .. ln*4+3
    float4 o = reinterpret_cast<const float4*>(bias)[ln];
#pragma unroll
    for (int k = 0; k < D; k++) {
        const float  s = srow[grp][k];
        const float4 w = sW4[k * 16 + ln];
        o.x = fmaf(s, w.x, o.x);
        o.y = fmaf(s, w.y, o.y);
        o.z = fmaf(s, w.z, o.z);
        o.w = fmaf(s, w.w, o.w);
    }
    o.x = (o.x > 0.f) ? o.x : LEAKY * o.x;
    o.y = (o.y > 0.f) ? o.y : LEAKY * o.y;
    o.z = (o.z > 0.f) ? o.z : LEAKY * o.z;
    o.w = (o.w > 0.f) ? o.w : LEAKY * o.w;

    reinterpret_cast<float4*>(out)[node * (D / 4) + ln] = o;
}

extern "C" void kernel_launch(void* const* d_in, const int* in_sizes, int n_in,
                              void* d_out, int out_size) {
    const float* x    = (const float*)d_in[0];   // node_features [N1, D]
    const float* WQ   = (const float*)d_in[1];   // [D, D]
    const float* bQ   = (const float*)d_in[2];   // [D]
    const float* WM   = (const float*)d_in[3];   // [D, D]
    const float* bM   = (const float*)d_in[4];   // [D]
    const int*   src1 = (const int*)d_in[5];     // [E1]
    const int*   dst1 = (const int*)d_in[6];     // [E1]
    const int*   src2 = (const int*)d_in[7];     // [E2]
    const int*   dst2 = (const int*)d_in[8];     // [E2]
    float* out = (float*)d_out;                  // [N2, D]

    // 1. zero degree counters
    zero_kernel<<<200, 256>>>();

    // 2. degree histograms
    degrees_kernel<<<(E2 + 255) / 256, 256>>>(src1, dst1, src2, dst2);

    // 3. norms
    norm_kernel<<<(NNODES + 255) / 256, 256>>>();

    // 4-6. exclusive scan of in-degrees -> CSR offsets + cursors
    scan_block_kernel<<<SCAN_NBLOCKS, SCAN_THREADS>>>();
    scan_sums_kernel<<<1, 32>>>();
    scan_add_kernel<<<(NNODES + 255) / 256, 256>>>();

    // 7. CSR fill (counting sort by dst), norms folded into edge weights
    fill_kernel<<<(E2 + 255) / 256, 256>>>(src1, dst1, src2, dst2);

    // 8. conv1: gather + GEMM + leaky -> g_h1
    gather_gemm_kernel<1><<<(N1 + 15) / 16, 256>>>(x, WQ, bQ, nullptr);

    // 9. conv2: gather (mod-N1 tiled h1) + GEMM + leaky -> d_out
    gather_gemm_kernel<2><<<(N2 + 15) / 16, 256>>>(nullptr, WM, bM, out);
}

// round 6
// speedup vs baseline: 1.8771x; 1.3677x over previous
#include <cuda_runtime.h>

// Problem constants (match reference)
#define N1 50000
#define N_LAYERS 3
#define N2 (N1 * N_LAYERS)   // 150000
#define E1 800000
#define E2 2400000
#define NE (E1 + E2)         // 3200000
#define D  64
#define LEAKY 0.01f

#define NNODES (N1 + N2)     // 200000 (graph1 nodes, then graph2 nodes)

// scan config
#define SCAN_ITEMS 8
#define SCAN_THREADS 256
#define SCAN_BLOCK (SCAN_ITEMS * SCAN_THREADS)                  // 2048
#define SCAN_NBLOCKS ((NNODES + SCAN_BLOCK - 1) / SCAN_BLOCK)   // 98

// -------- scratch (device globals; no allocations allowed) --------
__device__ __align__(16) float g_h1[N1 * D];          // 12.8 MB (post-conv1 features)
__device__ __align__(16) float g_fw[N1 * D];          // 12.8 MB (x@WQ, then h1@WM)
__device__ __align__(16) int   g_outdeg[NNODES];
__device__ __align__(16) int   g_indeg[NNODES];
__device__ __align__(16) float g_norm_out[NNODES];
__device__ __align__(16) float g_norm_in[NNODES];
__device__ __align__(16) int   g_csr_off[NNODES];
__device__ __align__(16) int   g_cursor[NNODES];
__device__ __align__(16) int   g_blocksums[SCAN_NBLOCKS + 1];
__device__ __align__(16) int   g_blockoff[SCAN_NBLOCKS + 1];
__device__ __align__(16) int2  g_csr_e[NE];           // 25.6 MB: {feat row, w bits} per edge

// -------- kernel 1: zero degree counters --------
__global__ void zero_kernel() {
    const int nt  = gridDim.x * blockDim.x;
    const int tid = blockIdx.x * blockDim.x + threadIdx.x;
    for (int i = tid; i < NNODES; i += nt) { g_outdeg[i] = 0; g_indeg[i] = 0; }
}

// -------- kernel 2: degree histograms (int4 vectorized) --------
__global__ void degrees_kernel(const int4* __restrict__ s1, const int4* __restrict__ d1,
                               const int4* __restrict__ s2, const int4* __restrict__ d2) {
    const int t = blockIdx.x * blockDim.x + threadIdx.x;
    if (t < E1 / 4) {
        const int4 s = s1[t], d = d1[t];
        atomicAdd(&g_outdeg[s.x], 1); atomicAdd(&g_outdeg[s.y], 1);
        atomicAdd(&g_outdeg[s.z], 1); atomicAdd(&g_outdeg[s.w], 1);
        atomicAdd(&g_indeg[d.x], 1);  atomicAdd(&g_indeg[d.y], 1);
        atomicAdd(&g_indeg[d.z], 1);  atomicAdd(&g_indeg[d.w], 1);
    }
    if (t < E2 / 4) {
        const int4 s = s2[t], d = d2[t];
        atomicAdd(&g_outdeg[N1 + s.x], 1); atomicAdd(&g_outdeg[N1 + s.y], 1);
        atomicAdd(&g_outdeg[N1 + s.z], 1); atomicAdd(&g_outdeg[N1 + s.w], 1);
        atomicAdd(&g_indeg[N1 + d.x], 1);  atomicAdd(&g_indeg[N1 + d.y], 1);
        atomicAdd(&g_indeg[N1 + d.z], 1);  atomicAdd(&g_indeg[N1 + d.w], 1);
    }
}

// -------- kernel 3: degree -> rsqrt norms --------
__global__ void norm_kernel() {
    const int t = blockIdx.x * blockDim.x + threadIdx.x;
    if (t < NNODES) {
        g_norm_out[t] = rsqrtf(fmaxf((float)g_outdeg[t], 1.f));
        g_norm_in[t]  = rsqrtf(fmaxf((float)g_indeg[t], 1.f));
    }
}

// -------- scan A: per-block exclusive scan of in-degrees (shuffle-based) --------
__global__ void scan_block_kernel() {
    __shared__ int sdata[SCAN_BLOCK];
    __shared__ int warpsums[8];
    const int b = blockIdx.x;
    const int t = threadIdx.x;
    const int base_g = b * SCAN_BLOCK;
    const int lane = t & 31;
    const int wid  = t >> 5;

    for (int i = t; i < SCAN_BLOCK; i += SCAN_THREADS) {
        const int gi = base_g + i;
        sdata[i] = (gi < NNODES) ? g_indeg[gi] : 0;
    }
    __syncthreads();

    int v[SCAN_ITEMS];
    int tsum = 0;
    const int lb = t * SCAN_ITEMS;
#pragma unroll
    for (int i = 0; i < SCAN_ITEMS; i++) { v[i] = sdata[lb + i]; tsum += v[i]; }

    // warp inclusive scan of per-thread sums
    int inc = tsum;
#pragma unroll
    for (int off = 1; off < 32; off <<= 1) {
        int n = __shfl_up_sync(0xFFFFFFFFu, inc, off);
        if (lane >= off) inc += n;
    }
    if (lane == 31) warpsums[wid] = inc;
    __syncthreads();

    if (wid == 0) {
        int s = (lane < 8) ? warpsums[lane] : 0;
#pragma unroll
        for (int off = 1; off < 8; off <<= 1) {
            int n = __shfl_up_sync(0xFFFFFFFFu, s, off);
            if (lane >= off) s += n;
        }
        if (lane < 8) warpsums[lane] = s;   // inclusive warp prefix
    }
    __syncthreads();

    const int wprefix = (wid == 0) ? 0 : warpsums[wid - 1];
    int running = wprefix + inc - tsum;     // exclusive prefix for this thread
    if (t == SCAN_THREADS - 1) g_blocksums[b] = wprefix + inc;

#pragma unroll
    for (int i = 0; i < SCAN_ITEMS; i++) { sdata[lb + i] = running; running += v[i]; }
    __syncthreads();
    for (int i = t; i < SCAN_BLOCK; i += SCAN_THREADS) {
        const int gi = base_g + i;
        if (gi < NNODES) g_csr_off[gi] = sdata[i];
    }
}

// -------- scan B: exclusive scan of block sums (one warp, shuffle) --------
__global__ void scan_sums_kernel() {
    const int lane = threadIdx.x;
    int carry = 0;
#pragma unroll
    for (int c = 0; c < (SCAN_NBLOCKS + 31) / 32; c++) {
        const int i = c * 32 + lane;
        const int val = (i < SCAN_NBLOCKS) ? g_blocksums[i] : 0;
        int inc = val;
#pragma unroll
        for (int off = 1; off < 32; off <<= 1) {
            int n = __shfl_up_sync(0xFFFFFFFFu, inc, off);
            if (lane >= off) inc += n;
        }
        if (i < SCAN_NBLOCKS) g_blockoff[i] = carry + inc - val;
        carry += __shfl_sync(0xFFFFFFFFu, inc, 31);
    }
}

// -------- scan C: add block offsets; init cursors --------
__global__ void scan_add_kernel() {
    const int t = blockIdx.x * blockDim.x + threadIdx.x;
    if (t < NNODES) {
        const int v = g_csr_off[t] + g_blockoff[t >> 11];   // SCAN_BLOCK == 2048
        g_csr_off[t] = v;
        g_cursor[t]  = v;
    }
}

// -------- CSR fill (counting sort by dst), int4 vectorized, packed stores --------
__global__ void fill_kernel(const int4* __restrict__ s1, const int4* __restrict__ d1,
                            const int4* __restrict__ s2, const int4* __restrict__ d2) {
    const int t = blockIdx.x * blockDim.x + threadIdx.x;
    if (t < E1 / 4) {
        const int4 s = s1[t], d = d1[t];
        const int sv[4] = {s.x, s.y, s.z, s.w};
        const int dv[4] = {d.x, d.y, d.z, d.w};
#pragma unroll
        for (int i = 0; i < 4; i++) {
            const int pos = atomicAdd(&g_cursor[dv[i]], 1);
            g_csr_e[pos] = make_int2(sv[i], __float_as_int(g_norm_out[sv[i]]));
        }
    }
    if (t < E2 / 4) {
        const int4 s = s2[t], d = d2[t];
        const int sv[4] = {s.x, s.y, s.z, s.w};
        const int dv[4] = {d.x, d.y, d.z, d.w};
#pragma unroll
        for (int i = 0; i < 4; i++) {
            int fi = sv[i];
            if (fi >= 2 * N1)  fi -= 2 * N1;   // tile(h1,(3,1)): row i -> h1[i mod N1]
            else if (fi >= N1) fi -= N1;
            const int pos = atomicAdd(&g_cursor[N1 + dv[i]], 1);
            g_csr_e[pos] = make_int2(fi, __float_as_int(g_norm_out[N1 + sv[i]]));
        }
    }
}

// -------- dense GEMM: g_fw[N1,64] = in[N1,64] @ W[64,64] (register-blocked) --------
// SRC=0: in = external x.  SRC=1: in = g_h1.  Output always g_fw.
// 128 threads: ln = tid&15 (4 output cols), g = tid>>4 (8-row chunk). 64 rows/block.
// smem: 16KB (W) + 16KB (rows) = 32KB < 48KB static limit.
template <int SRC>
__global__ void gemm_kernel(const float* __restrict__ in_ext, const float* __restrict__ W) {
    __shared__ float4 sW4[D * (D / 4)];       // 16 KB: W[k][*] as float4
    __shared__ float  srow[64 * D];           // 16 KB (no pad: reads are broadcast)

    const float* in = (SRC == 0) ? in_ext : g_h1;

    const int tid = threadIdx.x;
    const int ln  = tid & 15;
    const int g   = tid >> 4;                 // 0..7
    const int row0 = blockIdx.x * 64;

    for (int i = tid; i < D * D / 4; i += 128)
        sW4[i] = reinterpret_cast<const float4*>(W)[i];

    const float4 zero4 = make_float4(0.f, 0.f, 0.f, 0.f);
    for (int i = tid; i < 64 * 16; i += 128) {
        const int r = i >> 4, c = i & 15;
        const int gr = row0 + r;
        const float4 val = (gr < N1) ? reinterpret_cast<const float4*>(in)[gr * 16 + c] : zero4;
        *reinterpret_cast<float4*>(&srow[r * D + c * 4]) = val;
    }
    __syncthreads();

    float4 acc[8];
#pragma unroll
    for (int i = 0; i < 8; i++) acc[i] = zero4;

#pragma unroll 4
    for (int k = 0; k < D; k++) {
        const float4 w = sW4[k * 16 + ln];
#pragma unroll
        for (int i = 0; i < 8; i++) {
            const float s = srow[(g * 8 + i) * D + k];
            acc[i].x = fmaf(s, w.x, acc[i].x);
            acc[i].y = fmaf(s, w.y, acc[i].y);
            acc[i].z = fmaf(s, w.z, acc[i].z);
            acc[i].w = fmaf(s, w.w, acc[i].w);
        }
    }

#pragma unroll
    for (int i = 0; i < 8; i++) {
        const int r = row0 + g * 8 + i;
        if (r < N1) reinterpret_cast<float4*>(g_fw)[r * 16 + ln] = acc[i];
    }
}

// -------- pure gather + norm + bias + leaky (GEMM already applied to features) --------
// GRAPH=1: feat=g_fw (x@WQ), out=g_h1, nodes [0,N1)
// GRAPH=2: feat=g_fw (h1@WM), out=d_out, nodes [N1,N1+N2)
template <int GRAPH>
__global__ void gather_kernel(const float* __restrict__ bias,
                              float* __restrict__ out_ext) {
    const int tid = threadIdx.x;
    const int grp = tid >> 4;
    const int ln  = tid & 15;

    float* out     = (GRAPH == 1) ? g_h1 : out_ext;
    const int N    = (GRAPH == 1) ? N1 : N2;
    const int base = (GRAPH == 1) ? 0 : N1;

    const int node = blockIdx.x * 16 + grp;
    if (node >= N) return;
    const int gnode = base + node;

    const int start = g_csr_off[gnode];
    const int cnt   = g_indeg[gnode];
    const float nin = g_norm_in[gnode];
    const float4 b4 = reinterpret_cast<const float4*>(bias)[ln];

    const float4* f4 = reinterpret_cast<const float4*>(g_fw);

    float4 a0 = make_float4(0.f, 0.f, 0.f, 0.f);
    float4 a1 = make_float4(0.f, 0.f, 0.f, 0.f);
    int j = start;
    const int end = start + cnt;
    for (; j + 3 < end; j += 4) {
        const int2 e0 = g_csr_e[j],     e1 = g_csr_e[j + 1];
        const int2 e2 = g_csr_e[j + 2], e3 = g_csr_e[j + 3];
        const float4 v0 = f4[e0.x * 16 + ln];
        const float4 v1 = f4[e1.x * 16 + ln];
        const float4 v2 = f4[e2.x * 16 + ln];
        const float4 v3 = f4[e3.x * 16 + ln];
        const float w0 = __int_as_float(e0.y), w1 = __int_as_float(e1.y);
        const float w2 = __int_as_float(e2.y), w3 = __int_as_float(e3.y);
        a0.x = fmaf(w0, v0.x, fmaf(w1, v1.x, a0.x));
        a0.y = fmaf(w0, v0.y, fmaf(w1, v1.y, a0.y));
        a0.z = fmaf(w0, v0.z, fmaf(w1, v1.z, a0.z));
        a0.w = fmaf(w0, v0.w, fmaf(w1, v1.w, a0.w));
        a1.x = fmaf(w2, v2.x, fmaf(w3, v3.x, a1.x));
        a1.y = fmaf(w2, v2.y, fmaf(w3, v3.y, a1.y));
        a1.z = fmaf(w2, v2.z, fmaf(w3, v3.z, a1.z));
        a1.w = fmaf(w2, v2.w, fmaf(w3, v3.w, a1.w));
    }
    for (; j < end; j++) {
        const int2 e0 = g_csr_e[j];
        const float4 v0 = f4[e0.x * 16 + ln];
        const float w0 = __int_as_float(e0.y);
        a0.x = fmaf(w0, v0.x, a0.x);
        a0.y = fmaf(w0, v0.y, a0.y);
        a0.z = fmaf(w0, v0.z, a0.z);
        a0.w = fmaf(w0, v0.w, a0.w);
    }

    float4 o;
    o.x = fmaf(nin, a0.x + a1.x, b4.x);
    o.y = fmaf(nin, a0.y + a1.y, b4.y);
    o.z = fmaf(nin, a0.z + a1.z, b4.z);
    o.w = fmaf(nin, a0.w + a1.w, b4.w);
    o.x = (o.x > 0.f) ? o.x : LEAKY * o.x;
    o.y = (o.y > 0.f) ? o.y : LEAKY * o.y;
    o.z = (o.z > 0.f) ? o.z : LEAKY * o.z;
    o.w = (o.w > 0.f) ? o.w : LEAKY * o.w;

    reinterpret_cast<float4*>(out)[node * 16 + ln] = o;
}

extern "C" void kernel_launch(void* const* d_in, const int* in_sizes, int n_in,
                              void* d_out, int out_size) {
    const float* x    = (const float*)d_in[0];
    const float* WQ   = (const float*)d_in[1];
    const float* bQ   = (const float*)d_in[2];
    const float* WM   = (const float*)d_in[3];
    const float* bM   = (const float*)d_in[4];
    const int*   src1 = (const int*)d_in[5];
    const int*   dst1 = (const int*)d_in[6];
    const int*   src2 = (const int*)d_in[7];
    const int*   dst2 = (const int*)d_in[8];
    float* out = (float*)d_out;

    // 1. zero degree counters
    zero_kernel<<<200, 256>>>();
    // 2. degrees (4 edges/thread)
    degrees_kernel<<<(E2 / 4 + 255) / 256, 256>>>((const int4*)src1, (const int4*)dst1,
                                                  (const int4*)src2, (const int4*)dst2);
    // 3. norms
    norm_kernel<<<(NNODES + 255) / 256, 256>>>();
    // 4-6. exclusive scan -> CSR offsets + cursors
    scan_block_kernel<<<SCAN_NBLOCKS, SCAN_THREADS>>>();
    scan_sums_kernel<<<1, 32>>>();
    scan_add_kernel<<<(NNODES + 255) / 256, 256>>>();
    // 7. CSR fill
    fill_kernel<<<(E2 / 4 + 255) / 256, 256>>>((const int4*)src1, (const int4*)dst1,
                                               (const int4*)src2, (const int4*)dst2);

    // 8. g_fw = x @ WQ
    gemm_kernel<0><<<(N1 + 63) / 64, 128>>>(x, WQ);
    // 9. conv1 gather: g_h1 = leaky(nin * gather(g_fw) + bQ)
    gather_kernel<1><<<(N1 + 15) / 16, 256>>>(bQ, nullptr);
    // 10. g_fw = g_h1 @ WM
    gemm_kernel<1><<<(N1 + 63) / 64, 128>>>(nullptr, WM);
    // 11. conv2 gather: out = leaky(nin * gather(g_fw) + bM)
    gather_kernel<2><<<(N2 + 15) / 16, 256>>>(bM, out);
}

// round 7
// speedup vs baseline: 2.0126x; 1.0722x over previous
#include <cuda_runtime.h>

// Problem constants (match reference)
#define N1 50000
#define N_LAYERS 3
#define N2 (N1 * N_LAYERS)   // 150000
#define E1 800000
#define E2 2400000
#define NE (E1 + E2)         // 3200000
#define D  64
#define LEAKY 0.01f

#define NNODES (N1 + N2)     // 200000 (graph1 nodes, then graph2 nodes)

// scan config
#define SCAN_ITEMS 8
#define SCAN_THREADS 256
#define SCAN_BLOCK (SCAN_ITEMS * SCAN_THREADS)                  // 2048
#define SCAN_NBLOCKS ((NNODES + SCAN_BLOCK - 1) / SCAN_BLOCK)   // 98

// -------- scratch (device globals; no allocations allowed) --------
__device__ __align__(16) float g_h1[N1 * D];          // 12.8 MB (post-conv1 features)
__device__ __align__(16) float g_fw[N_LAYERS * N1 * D]; // 38.4 MB (scaled feature tables)
__device__ __align__(16) int   g_outdeg[NNODES];
__device__ __align__(16) int   g_indeg[NNODES];
__device__ __align__(16) float g_norm_out[NNODES];
__device__ __align__(16) float g_norm_in[NNODES];
__device__ __align__(16) int   g_csr_off[NNODES];
__device__ __align__(16) int   g_cursor[NNODES];
__device__ __align__(16) int   g_blocksums[SCAN_NBLOCKS + 1];
__device__ __align__(16) int   g_blockoff[SCAN_NBLOCKS + 1];
__device__ __align__(16) int   g_csr[NE];             // 12.8 MB: feature-row index per edge

// -------- kernel 1: zero degree counters --------
__global__ void zero_kernel() {
    const int nt  = gridDim.x * blockDim.x;
    const int tid = blockIdx.x * blockDim.x + threadIdx.x;
    for (int i = tid; i < NNODES; i += nt) { g_outdeg[i] = 0; g_indeg[i] = 0; }
}

// -------- kernel 2: degree histograms (int4 vectorized) --------
__global__ void degrees_kernel(const int4* __restrict__ s1, const int4* __restrict__ d1,
                               const int4* __restrict__ s2, const int4* __restrict__ d2) {
    const int t = blockIdx.x * blockDim.x + threadIdx.x;
    if (t < E1 / 4) {
        const int4 s = s1[t], d = d1[t];
        atomicAdd(&g_outdeg[s.x], 1); atomicAdd(&g_outdeg[s.y], 1);
        atomicAdd(&g_outdeg[s.z], 1); atomicAdd(&g_outdeg[s.w], 1);
        atomicAdd(&g_indeg[d.x], 1);  atomicAdd(&g_indeg[d.y], 1);
        atomicAdd(&g_indeg[d.z], 1);  atomicAdd(&g_indeg[d.w], 1);
    }
    if (t < E2 / 4) {
        const int4 s = s2[t], d = d2[t];
        atomicAdd(&g_outdeg[N1 + s.x], 1); atomicAdd(&g_outdeg[N1 + s.y], 1);
        atomicAdd(&g_outdeg[N1 + s.z], 1); atomicAdd(&g_outdeg[N1 + s.w], 1);
        atomicAdd(&g_indeg[N1 + d.x], 1);  atomicAdd(&g_indeg[N1 + d.y], 1);
        atomicAdd(&g_indeg[N1 + d.z], 1);  atomicAdd(&g_indeg[N1 + d.w], 1);
    }
}

// -------- scan A: per-block exclusive scan of in-degrees (shuffle-based) --------
__global__ void scan_block_kernel() {
    __shared__ int sdata[SCAN_BLOCK];
    __shared__ int warpsums[8];
    const int b = blockIdx.x;
    const int t = threadIdx.x;
    const int base_g = b * SCAN_BLOCK;
    const int lane = t & 31;
    const int wid  = t >> 5;

    for (int i = t; i < SCAN_BLOCK; i += SCAN_THREADS) {
        const int gi = base_g + i;
        sdata[i] = (gi < NNODES) ? g_indeg[gi] : 0;
    }
    __syncthreads();

    int v[SCAN_ITEMS];
    int tsum = 0;
    const int lb = t * SCAN_ITEMS;
#pragma unroll
    for (int i = 0; i < SCAN_ITEMS; i++) { v[i] = sdata[lb + i]; tsum += v[i]; }

    int inc = tsum;
#pragma unroll
    for (int off = 1; off < 32; off <<= 1) {
        int n = __shfl_up_sync(0xFFFFFFFFu, inc, off);
        if (lane >= off) inc += n;
    }
    if (lane == 31) warpsums[wid] = inc;
    __syncthreads();

    if (wid == 0) {
        int s = (lane < 8) ? warpsums[lane] : 0;
#pragma unroll
        for (int off = 1; off < 8; off <<= 1) {
            int n = __shfl_up_sync(0xFFFFFFFFu, s, off);
            if (lane >= off) s += n;
        }
        if (lane < 8) warpsums[lane] = s;
    }
    __syncthreads();

    const int wprefix = (wid == 0) ? 0 : warpsums[wid - 1];
    int running = wprefix + inc - tsum;
    if (t == SCAN_THREADS - 1) g_blocksums[b] = wprefix + inc;

#pragma unroll
    for (int i = 0; i < SCAN_ITEMS; i++) { sdata[lb + i] = running; running += v[i]; }
    __syncthreads();
    for (int i = t; i < SCAN_BLOCK; i += SCAN_THREADS) {
        const int gi = base_g + i;
        if (gi < NNODES) g_csr_off[gi] = sdata[i];
    }
}

// -------- scan B: exclusive scan of block sums (one warp, shuffle) --------
__global__ void scan_sums_kernel() {
    const int lane = threadIdx.x;
    int carry = 0;
#pragma unroll
    for (int c = 0; c < (SCAN_NBLOCKS + 31) / 32; c++) {
        const int i = c * 32 + lane;
        const int val = (i < SCAN_NBLOCKS) ? g_blocksums[i] : 0;
        int inc = val;
#pragma unroll
        for (int off = 1; off < 32; off <<= 1) {
            int n = __shfl_up_sync(0xFFFFFFFFu, inc, off);
            if (lane >= off) inc += n;
        }
        if (i < SCAN_NBLOCKS) g_blockoff[i] = carry + inc - val;
        carry += __shfl_sync(0xFFFFFFFFu, inc, 31);
    }
}

// -------- scan C: add block offsets, init cursors, compute norms --------
__global__ void scan_add_norm_kernel() {
    const int t = blockIdx.x * blockDim.x + threadIdx.x;
    if (t < NNODES) {
        const int v = g_csr_off[t] + g_blockoff[t >> 11];   // SCAN_BLOCK == 2048
        g_csr_off[t] = v;
        g_cursor[t]  = v;
        g_norm_out[t] = rsqrtf(fmaxf((float)g_outdeg[t], 1.f));
        g_norm_in[t]  = rsqrtf(fmaxf((float)g_indeg[t], 1.f));
    }
}

// -------- CSR fill: counting sort by dst; stores feature-row index only --------
__global__ void fill_kernel(const int4* __restrict__ s1, const int4* __restrict__ d1,
                            const int4* __restrict__ s2, const int4* __restrict__ d2) {
    const int t = blockIdx.x * blockDim.x + threadIdx.x;
    if (t < E1 / 4) {
        const int4 s = s1[t], d = d1[t];
        const int sv[4] = {s.x, s.y, s.z, s.w};
        const int dv[4] = {d.x, d.y, d.z, d.w};
#pragma unroll
        for (int i = 0; i < 4; i++) {
            const int pos = atomicAdd(&g_cursor[dv[i]], 1);
            g_csr[pos] = sv[i];                  // row in g_fw[0:N1)
        }
    }
    if (t < E2 / 4) {
        const int4 s = s2[t], d = d2[t];
        const int sv[4] = {s.x, s.y, s.z, s.w};
        const int dv[4] = {d.x, d.y, d.z, d.w};
#pragma unroll
        for (int i = 0; i < 4; i++) {
            const int pos = atomicAdd(&g_cursor[N1 + dv[i]], 1);
            g_csr[pos] = sv[i];                  // row in g_fw[0:3*N1) (layer-scaled table)
        }
    }
}

// -------- dense GEMM with norm-scaled epilogue --------
// SRC=0: in = external x;  writes g_fw[r] = norm_out1[r] * (x@WQ)[r]
// SRC=1: in = g_h1;        writes g_fw[l*N1+r] = norm_out2[l*N1+r] * (h1@WM)[r], l=0..2
// 128 threads: ln = tid&15 (4 output cols), g = tid>>4 (8-row chunk). 64 rows/block.
template <int SRC>
__global__ void gemm_kernel(const float* __restrict__ in_ext, const float* __restrict__ W) {
    __shared__ float4 sW4[D * (D / 4)];       // 16 KB
    __shared__ float  srow[64 * D];           // 16 KB (reads are broadcast; no pad needed)

    const float* in = (SRC == 0) ? in_ext : g_h1;

    const int tid = threadIdx.x;
    const int ln  = tid & 15;
    const int g   = tid >> 4;                 // 0..7
    const int row0 = blockIdx.x * 64;

    for (int i = tid; i < D * D / 4; i += 128)
        sW4[i] = reinterpret_cast<const float4*>(W)[i];

    const float4 zero4 = make_float4(0.f, 0.f, 0.f, 0.f);
    for (int i = tid; i < 64 * 16; i += 128) {
        const int r = i >> 4, c = i & 15;
        const int gr = row0 + r;
        const float4 val = (gr < N1) ? reinterpret_cast<const float4*>(in)[gr * 16 + c] : zero4;
        *reinterpret_cast<float4*>(&srow[r * D + c * 4]) = val;
    }
    __syncthreads();

    float4 acc[8];
#pragma unroll
    for (int i = 0; i < 8; i++) acc[i] = zero4;

#pragma unroll 4
    for (int k = 0; k < D; k++) {
        const float4 w = sW4[k * 16 + ln];
#pragma unroll
        for (int i = 0; i < 8; i++) {
            const float s = srow[(g * 8 + i) * D + k];
            acc[i].x = fmaf(s, w.x, acc[i].x);
            acc[i].y = fmaf(s, w.y, acc[i].y);
            acc[i].z = fmaf(s, w.z, acc[i].z);
            acc[i].w = fmaf(s, w.w, acc[i].w);
        }
    }

#pragma unroll
    for (int i = 0; i < 8; i++) {
        const int r = row0 + g * 8 + i;
        if (r < N1) {
            if (SRC == 0) {
                const float sc = g_norm_out[r];
                float4 o = acc[i];
                o.x *= sc; o.y *= sc; o.z *= sc; o.w *= sc;
                reinterpret_cast<float4*>(g_fw)[r * 16 + ln] = o;
            } else {
#pragma unroll
                for (int l = 0; l < N_LAYERS; l++) {
                    const float sc = g_norm_out[N1 + l * N1 + r];
                    float4 o = acc[i];
                    o.x *= sc; o.y *= sc; o.z *= sc; o.w *= sc;
                    reinterpret_cast<float4*>(g_fw)[(l * N1 + r) * 16 + ln] = o;
                }
            }
        }
    }
}

// -------- pure gather (weights pre-folded into rows) + norm_in + bias + leaky --------
// GRAPH=1: out=g_h1, nodes [0,N1), rows in [0,N1)
// GRAPH=2: out=d_out, nodes [N1,N1+N2), rows in [0,3*N1)
template <int GRAPH>
__global__ void gather_kernel(const float* __restrict__ bias,
                              float* __restrict__ out_ext) {
    const int tid = threadIdx.x;
    const int grp = tid >> 4;
    const int ln  = tid & 15;

    float* out     = (GRAPH == 1) ? g_h1 : out_ext;
    const int N    = (GRAPH == 1) ? N1 : N2;
    const int base = (GRAPH == 1) ? 0 : N1;

    const int node = blockIdx.x * 16 + grp;
    if (node >= N) return;
    const int gnode = base + node;

    const int start = g_csr_off[gnode];
    const int cnt   = g_indeg[gnode];
    const float nin = g_norm_in[gnode];
    const float4 b4 = reinterpret_cast<const float4*>(bias)[ln];

    const float4* f4 = reinterpret_cast<const float4*>(g_fw);

    float4 a0 = make_float4(0.f, 0.f, 0.f, 0.f);
    float4 a1 = make_float4(0.f, 0.f, 0.f, 0.f);
    int j = start;
    const int end = start + cnt;
    for (; j + 3 < end; j += 4) {
        const int i0 = g_csr[j],     i1 = g_csr[j + 1];
        const int i2 = g_csr[j + 2], i3 = g_csr[j + 3];
        const float4 v0 = f4[i0 * 16 + ln];
        const float4 v1 = f4[i1 * 16 + ln];
        const float4 v2 = f4[i2 * 16 + ln];
        const float4 v3 = f4[i3 * 16 + ln];
        a0.x += v0.x + v1.x;  a0.y += v0.y + v1.y;
        a0.z += v0.z + v1.z;  a0.w += v0.w + v1.w;
        a1.x += v2.x + v3.x;  a1.y += v2.y + v3.y;
        a1.z += v2.z + v3.z;  a1.w += v2.w + v3.w;
    }
    for (; j < end; j++) {
        const float4 v0 = f4[g_csr[j] * 16 + ln];
        a0.x += v0.x; a0.y += v0.y; a0.z += v0.z; a0.w += v0.w;
    }

    float4 o;
    o.x = fmaf(nin, a0.x + a1.x, b4.x);
    o.y = fmaf(nin, a0.y + a1.y, b4.y);
    o.z = fmaf(nin, a0.z + a1.z, b4.z);
    o.w = fmaf(nin, a0.w + a1.w, b4.w);
    o.x = (o.x > 0.f) ? o.x : LEAKY * o.x;
    o.y = (o.y > 0.f) ? o.y : LEAKY * o.y;
    o.z = (o.z > 0.f) ? o.z : LEAKY * o.z;
    o.w = (o.w > 0.f) ? o.w : LEAKY * o.w;

    reinterpret_cast<float4*>(out)[node * 16 + ln] = o;
}

extern "C" void kernel_launch(void* const* d_in, const int* in_sizes, int n_in,
                              void* d_out, int out_size) {
    const float* x    = (const float*)d_in[0];
    const float* WQ   = (const float*)d_in[1];
    const float* bQ   = (const float*)d_in[2];
    const float* WM   = (const float*)d_in[3];
    const float* bM   = (const float*)d_in[4];
    const int*   src1 = (const int*)d_in[5];
    const int*   dst1 = (const int*)d_in[6];
    const int*   src2 = (const int*)d_in[7];
    const int*   dst2 = (const int*)d_in[8];
    float* out = (float*)d_out;

    // 1. zero degree counters
    zero_kernel<<<200, 256>>>();
    // 2. degrees (4 edges/thread)
    degrees_kernel<<<(E2 / 4 + 255) / 256, 256>>>((const int4*)src1, (const int4*)dst1,
                                                  (const int4*)src2, (const int4*)dst2);
    // 3-5. exclusive scan -> CSR offsets + cursors + norms
    scan_block_kernel<<<SCAN_NBLOCKS, SCAN_THREADS>>>();
    scan_sums_kernel<<<1, 32>>>();
    scan_add_norm_kernel<<<(NNODES + 255) / 256, 256>>>();
    // 6. CSR fill (indices only)
    fill_kernel<<<(E2 / 4 + 255) / 256, 256>>>((const int4*)src1, (const int4*)dst1,
                                               (const int4*)src2, (const int4*)dst2);

    // 7. g_fw[0:N1) = norm_out1 * (x @ WQ)
    gemm_kernel<0><<<(N1 + 63) / 64, 128>>>(x, WQ);
    // 8. conv1 gather: g_h1 = leaky(nin * sum + bQ)
    gather_kernel<1><<<(N1 + 15) / 16, 256>>>(bQ, nullptr);
    // 9. g_fw[0:3*N1) = per-layer norm_out2 * (h1 @ WM)
    gemm_kernel<1><<<(N1 + 63) / 64, 128>>>(nullptr, WM);
    // 10. conv2 gather: out = leaky(nin * sum + bM)
    gather_kernel<2><<<(N2 + 15) / 16, 256>>>(bM, out);
}